// round 14
// baseline (speedup 1.0000x reference)
#include <cuda_runtime.h>
#include <cuda_fp16.h>
#include <cstdint>

#define N_NODES  100000
#define N_EDGES  1600000
#define N_GRAPHS 512
#define NB_SCAN  ((N_NODES + 1023) / 1024)   // 98
#define N_TILES  (N_NODES / 16)              // 6250 (exact)
#define PRE_BLKS ((N_NODES + 255) / 256)     // 391
#define HIST_BLKS ((N_EDGES / 4 + 255) / 256) // 1563
#define FILL_BLKS ((N_EDGES / 8 + 255) / 256) // 782

// ---------------- device scratch (no allocations allowed) ----------------
// g_cnt is zero-initialized at load and re-zeroed at the END of each call
// (in k_head), so k_prehist can run pre+hist concurrently.
__device__ __half2 g_h0h[N_NODES * 16];     // h0 fp16 pairs (64B/row)
__device__ __half2 g_h1h[N_NODES * 32];     // h1 fp16 pairs (128B/row)
__device__ __half2 g_h2h[N_NODES * 32];     // h2 fp16 pairs (128B/row)
__device__ int     g_cnt[N_NODES];
__device__ int     g_rs[N_NODES];
__device__ int     g_cur[N_NODES];
__device__ int     g_adj[N_EDGES];
__device__ int     g_bsum[NB_SCAN + 8];
__device__ int     g_lo[N_GRAPHS + 1];

// ---------------- mma helpers ----------------
__device__ __forceinline__ uint32_t smem_u32(const void* p) {
    return (uint32_t)__cvta_generic_to_shared(p);
}
__device__ __forceinline__ void ldsm_x4(uint32_t& a0, uint32_t& a1,
                                        uint32_t& a2, uint32_t& a3, uint32_t addr) {
    asm volatile("ldmatrix.sync.aligned.m8n8.x4.shared.b16 {%0,%1,%2,%3}, [%4];"
                 : "=r"(a0), "=r"(a1), "=r"(a2), "=r"(a3) : "r"(addr));
}
__device__ __forceinline__ void ldsm_x2t(uint32_t& b0, uint32_t& b1, uint32_t addr) {
    asm volatile("ldmatrix.sync.aligned.m8n8.x2.trans.shared.b16 {%0,%1}, [%2];"
                 : "=r"(b0), "=r"(b1) : "r"(addr));
}
__device__ __forceinline__ void mma16816(float c[4], uint32_t a0, uint32_t a1,
                                         uint32_t a2, uint32_t a3,
                                         uint32_t b0, uint32_t b1) {
    asm volatile("mma.sync.aligned.m16n8k16.row.col.f32.f16.f16.f32 "
                 "{%0,%1,%2,%3}, {%4,%5,%6,%7}, {%8,%9}, {%0,%1,%2,%3};"
                 : "+f"(c[0]), "+f"(c[1]), "+f"(c[2]), "+f"(c[3])
                 : "r"(a0), "r"(a1), "r"(a2), "r"(a3), "r"(b0), "r"(b1));
}

// ---------------- fused pre (blocks 0..390) + hist (rest) ----------------
__global__ void k_prehist(const float* __restrict__ x,
                          const float* __restrict__ w,
                          const float* __restrict__ b,
                          const int* __restrict__ dst) {
    int t = threadIdx.x;
    if (blockIdx.x < PRE_BLKS) {
        __shared__ float sw[5 * 32];
        __shared__ float sb[32];
        if (t < 160) sw[t] = w[t];
        if (t < 32)  sb[t] = b[t];
        __syncthreads();
        int n = blockIdx.x * 256 + t;
        if (n >= N_NODES) return;
        float xi[5];
#pragma unroll
        for (int i = 0; i < 5; i++) xi[i] = x[n * 5 + i];
        __half2 hv[16];
#pragma unroll
        for (int j2 = 0; j2 < 16; j2++) {
            float o0 = sb[2 * j2], o1 = sb[2 * j2 + 1];
#pragma unroll
            for (int i = 0; i < 5; i++) {
                o0 += xi[i] * sw[i * 32 + 2 * j2];
                o1 += xi[i] * sw[i * 32 + 2 * j2 + 1];
            }
            hv[j2] = __floats2half2_rn(fmaxf(o0, 0.f), fmaxf(o1, 0.f));
        }
        uint4* dstp = (uint4*)&g_h0h[n * 16];
        dstp[0] = ((uint4*)hv)[0];
        dstp[1] = ((uint4*)hv)[1];
        dstp[2] = ((uint4*)hv)[2];
        dstp[3] = ((uint4*)hv)[3];
    } else {
        int i = (blockIdx.x - PRE_BLKS) * 256 + t;
        int e4 = i * 4;
        if (e4 + 3 < N_EDGES) {
            int4 d = *(const int4*)&dst[e4];
            atomicAdd(&g_cnt[d.x], 1);
            atomicAdd(&g_cnt[d.y], 1);
            atomicAdd(&g_cnt[d.z], 1);
            atomicAdd(&g_cnt[d.w], 1);
        } else if (e4 < N_EDGES) {
            for (int e = e4; e < N_EDGES; e++) atomicAdd(&g_cnt[dst[e]], 1);
        }
    }
}

__global__ void k_scan1() {
    __shared__ int wsum[8];
    int b = blockIdx.x, t = threadIdx.x;
    int lane = t & 31, w = t >> 5;
    int base = b * 1024 + t * 4;
    int v[4];
#pragma unroll
    for (int q = 0; q < 4; q++) v[q] = (base + q < N_NODES) ? g_cnt[base + q] : 0;
    int tot = v[0] + v[1] + v[2] + v[3];
    int sc = tot;
#pragma unroll
    for (int o = 1; o < 32; o <<= 1) {
        int x = __shfl_up_sync(0xffffffffu, sc, o);
        if (lane >= o) sc += x;
    }
    if (lane == 31) wsum[w] = sc;
    __syncthreads();
    if (t == 0) {
        int r = 0;
#pragma unroll
        for (int i = 0; i < 8; i++) { int x = wsum[i]; wsum[i] = r; r += x; }
        g_bsum[b] = r;
    }
    __syncthreads();
    int run = wsum[w] + (sc - tot);
#pragma unroll
    for (int q = 0; q < 4; q++) {
        if (base + q < N_NODES) g_rs[base + q] = run;
        run += v[q];
    }
}

// scan3 with embedded scan2 (each block redundantly scans the 98 sums) + bounds
__global__ void k_scan23(const int* __restrict__ batch) {
    __shared__ int psum[NB_SCAN];
    int t = threadIdx.x;
    if (t < NB_SCAN) psum[t] = g_bsum[t];
    __syncthreads();
    if (t == 0) {
        int r = 0;
#pragma unroll 7
        for (int i = 0; i < NB_SCAN; i++) { int x = psum[i]; psum[i] = r; r += x; }
    }
    __syncthreads();
    int i = blockIdx.x * 256 + t;
    if (i >= N_NODES) return;
    int v = g_rs[i] + psum[i >> 10];
    g_rs[i] = v;
    g_cur[i] = v;
    int b = batch[i];
    int bn = (i + 1 < N_NODES) ? batch[i + 1] : N_GRAPHS;
    if (i == 0)
        for (int g = 0; g <= b; g++) g_lo[g] = 0;
    for (int g = b + 1; g <= bn; g++) g_lo[g] = i + 1;
}

// 8 edges / thread: 8 independent atomic+store chains for latency hiding
__global__ void k_fill(const int* __restrict__ src, const int* __restrict__ dst) {
    int i = blockIdx.x * blockDim.x + threadIdx.x;
    int e8 = i * 8;
    if (e8 + 7 < N_EDGES) {
        int4 s0 = *(const int4*)&src[e8];
        int4 s1 = *(const int4*)&src[e8 + 4];
        int4 d0 = *(const int4*)&dst[e8];
        int4 d1 = *(const int4*)&dst[e8 + 4];
        int p0 = atomicAdd(&g_cur[d0.x], 1);
        int p1 = atomicAdd(&g_cur[d0.y], 1);
        int p2 = atomicAdd(&g_cur[d0.z], 1);
        int p3 = atomicAdd(&g_cur[d0.w], 1);
        int p4 = atomicAdd(&g_cur[d1.x], 1);
        int p5 = atomicAdd(&g_cur[d1.y], 1);
        int p6 = atomicAdd(&g_cur[d1.z], 1);
        int p7 = atomicAdd(&g_cur[d1.w], 1);
        g_adj[p0] = s0.x; g_adj[p1] = s0.y;
        g_adj[p2] = s0.z; g_adj[p3] = s0.w;
        g_adj[p4] = s1.x; g_adj[p5] = s1.y;
        g_adj[p6] = s1.z; g_adj[p7] = s1.w;
    } else if (e8 < N_EDGES) {
        for (int e = e8; e < N_EDGES; e++)
            g_adj[atomicAdd(&g_cur[dst[e]], 1)] = src[e];
    }
}

// ---------------- conv1: 16-deep gather + tensor-core combine ------------
__global__ void __launch_bounds__(256) k_conv1(const float* __restrict__ wl,
                                               const float* __restrict__ bl,
                                               const float* __restrict__ wr) {
    extern __shared__ char dyn[];
    half*  sB    = (half*)dyn;                                  // 64*72
    half*  sA    = (half*)(dyn + 64 * 72 * 2);                  // 8*16*72
    float* sbias = (float*)(dyn + 64 * 72 * 2 + 8 * 16 * 72 * 2);
    int t = threadIdx.x;
    for (int i = t; i < 64 * 64; i += 256) {
        int k = i >> 6, n = i & 63;
        float v = (k < 32) ? wl[k * 64 + n] : wr[(k - 32) * 64 + n];
        sB[k * 72 + n] = __float2half(v);
    }
    if (t < 64) sbias[t] = bl[t];
    __syncthreads();

    int lane = t & 31, warp = t >> 5;
    int tile = blockIdx.x * 8 + warp;
    if (tile >= N_TILES) return;
    int base = tile * 16;
    half2* sa2 = (half2*)(sA + warp * 16 * 72);   // row stride 36 half2
    int l15 = lane & 15;
    bool hihalf = lane >= 16;

    for (int r = 0; r < 16; r++) {
        int n = base + r;
        int rs = g_rs[n], d = g_cnt[n];
        float2 ac0 = make_float2(0.f, 0.f), ac1 = make_float2(0.f, 0.f);
        float2 ac2 = make_float2(0.f, 0.f), ac3 = make_float2(0.f, 0.f);
        for (int j = 0; j < d; j += 32) {
            int chunk = min(32, d - j);
            int idx = (lane < chunk) ? g_adj[rs + j + lane] : 0;
            int q = 0;
            for (; q + 15 < chunk; q += 16) {   // 8 loads/lane in flight
                int v[16];
#pragma unroll
                for (int u = 0; u < 16; u++) v[u] = __shfl_sync(0xffffffffu, idx, q + u);
                int s0 = hihalf ? v[1]  : v[0];
                int s1 = hihalf ? v[3]  : v[2];
                int s2 = hihalf ? v[5]  : v[4];
                int s3 = hihalf ? v[7]  : v[6];
                int s4 = hihalf ? v[9]  : v[8];
                int s5 = hihalf ? v[11] : v[10];
                int s6 = hihalf ? v[13] : v[12];
                int s7 = hihalf ? v[15] : v[14];
                float2 f0 = __half22float2(g_h0h[s0 * 16 + l15]);
                float2 f1 = __half22float2(g_h0h[s1 * 16 + l15]);
                float2 f2 = __half22float2(g_h0h[s2 * 16 + l15]);
                float2 f3 = __half22float2(g_h0h[s3 * 16 + l15]);
                float2 f4 = __half22float2(g_h0h[s4 * 16 + l15]);
                float2 f5 = __half22float2(g_h0h[s5 * 16 + l15]);
                float2 f6 = __half22float2(g_h0h[s6 * 16 + l15]);
                float2 f7 = __half22float2(g_h0h[s7 * 16 + l15]);
                ac0.x += f0.x + f4.x; ac0.y += f0.y + f4.y;
                ac1.x += f1.x + f5.x; ac1.y += f1.y + f5.y;
                ac2.x += f2.x + f6.x; ac2.y += f2.y + f6.y;
                ac3.x += f3.x + f7.x; ac3.y += f3.y + f7.y;
            }
            for (; q + 7 < chunk; q += 8) {
                int nA = __shfl_sync(0xffffffffu, idx, q);
                int nB = __shfl_sync(0xffffffffu, idx, q + 1);
                int nC = __shfl_sync(0xffffffffu, idx, q + 2);
                int nD = __shfl_sync(0xffffffffu, idx, q + 3);
                int nE = __shfl_sync(0xffffffffu, idx, q + 4);
                int nF = __shfl_sync(0xffffffffu, idx, q + 5);
                int nG = __shfl_sync(0xffffffffu, idx, q + 6);
                int nH = __shfl_sync(0xffffffffu, idx, q + 7);
                int s0 = hihalf ? nB : nA;
                int s1 = hihalf ? nD : nC;
                int s2 = hihalf ? nF : nE;
                int s3 = hihalf ? nH : nG;
                float2 f0 = __half22float2(g_h0h[s0 * 16 + l15]);
                float2 f1 = __half22float2(g_h0h[s1 * 16 + l15]);
                float2 f2 = __half22float2(g_h0h[s2 * 16 + l15]);
                float2 f3 = __half22float2(g_h0h[s3 * 16 + l15]);
                ac0.x += f0.x; ac0.y += f0.y;
                ac1.x += f1.x; ac1.y += f1.y;
                ac2.x += f2.x; ac2.y += f2.y;
                ac3.x += f3.x; ac3.y += f3.y;
            }
            for (; q + 1 < chunk; q += 2) {
                int nA = __shfl_sync(0xffffffffu, idx, q);
                int nB = __shfl_sync(0xffffffffu, idx, q + 1);
                int s0 = hihalf ? nB : nA;
                float2 f0 = __half22float2(g_h0h[s0 * 16 + l15]);
                ac0.x += f0.x; ac0.y += f0.y;
            }
            if (q < chunk) {
                int nA = __shfl_sync(0xffffffffu, idx, q);
                if (!hihalf) {
                    float2 f0 = __half22float2(g_h0h[nA * 16 + l15]);
                    ac0.x += f0.x; ac0.y += f0.y;
                }
            }
        }
        ac0.x += ac1.x + ac2.x + ac3.x;
        ac0.y += ac1.y + ac2.y + ac3.y;
        ac0.x += __shfl_xor_sync(0xffffffffu, ac0.x, 16);
        ac0.y += __shfl_xor_sync(0xffffffffu, ac0.y, 16);
        float inv = d > 0 ? 1.0f / (float)d : 0.0f;
        if (!hihalf) {
            sa2[r * 36 + l15]      = __floats2half2_rn(ac0.x * inv, ac0.y * inv);
            sa2[r * 36 + 16 + l15] = g_h0h[n * 16 + l15];
        }
    }
    __syncwarp();

    // GEMM: [16 x 64] @ [64 x 64], fp32 accum
    uint32_t aBase = smem_u32(sA + warp * 16 * 72) + (uint32_t)((lane & 15) * 144 + (lane >> 4) * 16);
    uint32_t bBase = smem_u32(sB) + (uint32_t)((lane & 15) * 144);
    float c[8][4];
#pragma unroll
    for (int nt = 0; nt < 8; nt++) { c[nt][0] = c[nt][1] = c[nt][2] = c[nt][3] = 0.f; }
#pragma unroll
    for (int kk = 0; kk < 4; kk++) {
        uint32_t a0, a1, a2, a3;
        ldsm_x4(a0, a1, a2, a3, aBase + kk * 32);
#pragma unroll
        for (int nt = 0; nt < 8; nt++) {
            uint32_t b0, b1;
            ldsm_x2t(b0, b1, bBase + (uint32_t)(kk * 16 * 144 + nt * 16));
            mma16816(c[nt], a0, a1, a2, a3, b0, b1);
        }
    }
    int q = lane & 3, rlo = lane >> 2;
    float ssl = 0.f, ssh = 0.f;
#pragma unroll
    for (int nt = 0; nt < 8; nt++) {
        float b0 = sbias[nt * 8 + q * 2], b1 = sbias[nt * 8 + q * 2 + 1];
        c[nt][0] += b0; c[nt][1] += b1; c[nt][2] += b0; c[nt][3] += b1;
        ssl += c[nt][0] * c[nt][0] + c[nt][1] * c[nt][1];
        ssh += c[nt][2] * c[nt][2] + c[nt][3] * c[nt][3];
    }
    ssl += __shfl_xor_sync(0xffffffffu, ssl, 1);
    ssl += __shfl_xor_sync(0xffffffffu, ssl, 2);
    ssh += __shfl_xor_sync(0xffffffffu, ssh, 1);
    ssh += __shfl_xor_sync(0xffffffffu, ssh, 2);
    float il = 1.0f / fmaxf(sqrtf(ssl), 1e-12f);
    float ih = 1.0f / fmaxf(sqrtf(ssh), 1e-12f);
    int nlo = base + rlo, nhi = nlo + 8;
#pragma unroll
    for (int nt = 0; nt < 8; nt++) {
        g_h1h[nlo * 32 + nt * 4 + q] =
            __floats2half2_rn(fmaxf(c[nt][0] * il, 0.f), fmaxf(c[nt][1] * il, 0.f));
        g_h1h[nhi * 32 + nt * 4 + q] =
            __floats2half2_rn(fmaxf(c[nt][2] * ih, 0.f), fmaxf(c[nt][3] * ih, 0.f));
    }
}

// ---------------- conv2: 16-deep gather + tensor-core combine ------------
__global__ void __launch_bounds__(256) k_conv2(const float* __restrict__ wl,
                                               const float* __restrict__ bl,
                                               const float* __restrict__ wr) {
    extern __shared__ char dyn[];
    half*  sB    = (half*)dyn;                                   // 128*72
    half*  sA    = (half*)(dyn + 128 * 72 * 2);                  // 8*16*136
    float* sbias = (float*)(dyn + 128 * 72 * 2 + 8 * 16 * 136 * 2);
    int t = threadIdx.x;
    for (int i = t; i < 128 * 64; i += 256) {
        int k = i >> 6, n = i & 63;
        float v = (k < 64) ? wl[k * 64 + n] : wr[(k - 64) * 64 + n];
        sB[k * 72 + n] = __float2half(v);
    }
    if (t < 64) sbias[t] = bl[t];
    __syncthreads();

    int lane = t & 31, warp = t >> 5;
    int tile = blockIdx.x * 8 + warp;
    if (tile >= N_TILES) return;
    int base = tile * 16;
    half2* sa2 = (half2*)(sA + warp * 16 * 136);   // row stride 68 half2

    for (int r = 0; r < 16; r++) {
        int n = base + r;
        int rs = g_rs[n], d = g_cnt[n];
        float a0 = 0.f, b0 = 0.f, a1 = 0.f, b1 = 0.f;
        float a2 = 0.f, b2 = 0.f, a3 = 0.f, b3 = 0.f;
        for (int j = 0; j < d; j += 32) {
            int chunk = min(32, d - j);
            int idx = (lane < chunk) ? g_adj[rs + j + lane] : 0;
            int q = 0;
            for (; q + 15 < chunk; q += 16) {   // 16 loads/lane in flight
                int m[16];
#pragma unroll
                for (int u = 0; u < 16; u++) m[u] = __shfl_sync(0xffffffffu, idx, q + u);
                float2 f[16];
#pragma unroll
                for (int u = 0; u < 16; u++) f[u] = __half22float2(g_h1h[m[u] * 32 + lane]);
#pragma unroll
                for (int u = 0; u < 16; u += 4) {
                    a0 += f[u].x;     b0 += f[u].y;
                    a1 += f[u + 1].x; b1 += f[u + 1].y;
                    a2 += f[u + 2].x; b2 += f[u + 2].y;
                    a3 += f[u + 3].x; b3 += f[u + 3].y;
                }
            }
            for (; q + 3 < chunk; q += 4) {
                int m0 = __shfl_sync(0xffffffffu, idx, q);
                int m1 = __shfl_sync(0xffffffffu, idx, q + 1);
                int m2 = __shfl_sync(0xffffffffu, idx, q + 2);
                int m3 = __shfl_sync(0xffffffffu, idx, q + 3);
                float2 f0 = __half22float2(g_h1h[m0 * 32 + lane]);
                float2 f1 = __half22float2(g_h1h[m1 * 32 + lane]);
                float2 f2 = __half22float2(g_h1h[m2 * 32 + lane]);
                float2 f3 = __half22float2(g_h1h[m3 * 32 + lane]);
                a0 += f0.x; b0 += f0.y;
                a1 += f1.x; b1 += f1.y;
                a2 += f2.x; b2 += f2.y;
                a3 += f3.x; b3 += f3.y;
            }
            for (; q < chunk; q++) {
                int m0 = __shfl_sync(0xffffffffu, idx, q);
                float2 f0 = __half22float2(g_h1h[m0 * 32 + lane]);
                a0 += f0.x; b0 += f0.y;
            }
        }
        float inv = d > 0 ? 1.0f / (float)d : 0.0f;
        sa2[r * 68 + lane] =
            __floats2half2_rn((a0 + a1 + a2 + a3) * inv, (b0 + b1 + b2 + b3) * inv);
        sa2[r * 68 + 32 + lane] = g_h1h[n * 32 + lane];
    }
    __syncwarp();

    // GEMM: [16 x 128] @ [128 x 64], fp32 accum
    uint32_t aBase = smem_u32(sA + warp * 16 * 136) + (uint32_t)((lane & 15) * 272 + (lane >> 4) * 16);
    uint32_t bBase = smem_u32(sB) + (uint32_t)((lane & 15) * 144);
    float c[8][4];
#pragma unroll
    for (int nt = 0; nt < 8; nt++) { c[nt][0] = c[nt][1] = c[nt][2] = c[nt][3] = 0.f; }
#pragma unroll
    for (int kk = 0; kk < 8; kk++) {
        uint32_t a0, a1, a2, a3;
        ldsm_x4(a0, a1, a2, a3, aBase + kk * 32);
#pragma unroll
        for (int nt = 0; nt < 8; nt++) {
            uint32_t b0, b1;
            ldsm_x2t(b0, b1, bBase + (uint32_t)(kk * 16 * 144 + nt * 16));
            mma16816(c[nt], a0, a1, a2, a3, b0, b1);
        }
    }
    int q = lane & 3, rlo = lane >> 2;
    float ssl = 0.f, ssh = 0.f;
#pragma unroll
    for (int nt = 0; nt < 8; nt++) {
        float bb0 = sbias[nt * 8 + q * 2], bb1 = sbias[nt * 8 + q * 2 + 1];
        c[nt][0] += bb0; c[nt][1] += bb1; c[nt][2] += bb0; c[nt][3] += bb1;
        ssl += c[nt][0] * c[nt][0] + c[nt][1] * c[nt][1];
        ssh += c[nt][2] * c[nt][2] + c[nt][3] * c[nt][3];
    }
    ssl += __shfl_xor_sync(0xffffffffu, ssl, 1);
    ssl += __shfl_xor_sync(0xffffffffu, ssl, 2);
    ssh += __shfl_xor_sync(0xffffffffu, ssh, 1);
    ssh += __shfl_xor_sync(0xffffffffu, ssh, 2);
    float il = 1.0f / fmaxf(sqrtf(ssl), 1e-12f);
    float ih = 1.0f / fmaxf(sqrtf(ssh), 1e-12f);
    int nlo = base + rlo, nhi = nlo + 8;
#pragma unroll
    for (int nt = 0; nt < 8; nt++) {
        g_h2h[nlo * 32 + nt * 4 + q] =
            __floats2half2_rn(fmaxf(c[nt][0] * il, 0.f), fmaxf(c[nt][1] * il, 0.f));
        g_h2h[nhi * 32 + nt * 4 + q] =
            __floats2half2_rn(fmaxf(c[nt][2] * ih, 0.f), fmaxf(c[nt][3] * ih, 0.f));
    }
}

// ---------------- head: pool + MLP; ALSO re-zeroes g_cnt for next call ---
__global__ void k_head(const float* __restrict__ p1w, const float* __restrict__ p1b,
                       const float* __restrict__ p2w, const float* __restrict__ p2b,
                       const float* __restrict__ ow,  const float* __restrict__ ob,
                       float* __restrict__ out) {
    __shared__ float part[4 * 64];
    __shared__ float sg[64], t1[64], t2[16];
    int g = blockIdx.x, t = threadIdx.x;
    int zi = g * 256 + t;
    if (zi < N_NODES) g_cnt[zi] = 0;

    int lo = g_lo[g], hi = g_lo[g + 1];
    int f = t & 63, r = t >> 6;
    float s = 0.f;
    for (int n = lo + r; n < hi; n += 4) {
        __half2 v = g_h2h[n * 32 + (f >> 1)];
        s += (f & 1) ? __half2float(__high2half(v)) : __half2float(__low2half(v));
    }
    part[r * 64 + f] = s;
    __syncthreads();
    if (t < 64) {
        float tot = part[t] + part[64 + t] + part[128 + t] + part[192 + t];
        float cnt = (float)(hi - lo);
        sg[t] = tot / fmaxf(cnt, 1.0f);
    }
    __syncthreads();
    if (t < 64) {
        float s1 = p1b[t];
#pragma unroll 8
        for (int k = 0; k < 64; k++) s1 += sg[k] * p1w[k * 64 + t];
        t1[t] = fmaxf(s1, 0.f);
    }
    __syncthreads();
    if (t < 16) {
        float s2 = p2b[t];
#pragma unroll 8
        for (int k = 0; k < 64; k++) s2 += t1[k] * p2w[k * 16 + t];
        t2[t] = fmaxf(s2, 0.f);
    }
    __syncthreads();
    if (t == 0) {
        float o = ob[0];
#pragma unroll
        for (int k = 0; k < 16; k++) o += t2[k] * ow[k];
        out[g] = o;
    }
}

// ---------------- launch ----------------
extern "C" void kernel_launch(void* const* d_in, const int* in_sizes, int n_in,
                              void* d_out, int out_size) {
    const float* x     = (const float*)d_in[0];
    const int*   ei    = (const int*)d_in[1];
    const int*   batch = (const int*)d_in[2];
    int base = (n_in >= 18 && in_sizes[3] == 1) ? 4 : 3;
    const float* pre_w = (const float*)d_in[base + 0];
    const float* pre_b = (const float*)d_in[base + 1];
    const float* c1_wl = (const float*)d_in[base + 2];
    const float* c1_bl = (const float*)d_in[base + 3];
    const float* c1_wr = (const float*)d_in[base + 4];
    const float* c2_wl = (const float*)d_in[base + 5];
    const float* c2_bl = (const float*)d_in[base + 6];
    const float* c2_wr = (const float*)d_in[base + 7];
    const float* p1_w  = (const float*)d_in[base + 8];
    const float* p1_b  = (const float*)d_in[base + 9];
    const float* p2_w  = (const float*)d_in[base + 10];
    const float* p2_b  = (const float*)d_in[base + 11];
    const float* o_w   = (const float*)d_in[base + 12];
    const float* o_b   = (const float*)d_in[base + 13];

    const int* src = ei;
    const int* dst = ei + N_EDGES;
    float* out = (float*)d_out;

    const size_t smem1 = 64 * 72 * 2 + 8 * 16 * 72 * 2 + 256;     // 27904
    const size_t smem2 = 128 * 72 * 2 + 8 * 16 * 136 * 2 + 256;   // 53504
    cudaFuncSetAttribute(k_conv1, cudaFuncAttributeMaxDynamicSharedMemorySize, (int)smem1);
    cudaFuncSetAttribute(k_conv2, cudaFuncAttributeMaxDynamicSharedMemorySize, (int)smem2);

    const int T = 256;
    k_prehist<<<PRE_BLKS + HIST_BLKS, T>>>(x, pre_w, pre_b, dst);
    k_scan1<<<NB_SCAN, 256>>>();
    k_scan23<<<PRE_BLKS, 256>>>(batch);
    k_fill<<<FILL_BLKS, T>>>(src, dst);

    int nblk = (N_TILES + 7) / 8;   // 782
    k_conv1<<<nblk, 256, smem1>>>(c1_wl, c1_bl, c1_wr);
    k_conv2<<<nblk, 256, smem2>>>(c2_wl, c2_bl, c2_wr);

    k_head<<<N_GRAPHS, 256>>>(p1_w, p1_b, p2_w, p2_b, o_w, o_b, out);
    (void)out_size;
}

// round 15
// speedup vs baseline: 1.0341x; 1.0341x over previous
#include <cuda_runtime.h>
#include <cuda_fp16.h>
#include <cstdint>

#define N_NODES  100000
#define N_EDGES  1600000
#define N_GRAPHS 512
#define NB_SCAN  ((N_NODES + 1023) / 1024)   // 98
#define N_TILES  (N_NODES / 16)              // 6250 (exact)
#define PRE_BLKS ((N_NODES + 255) / 256)     // 391
#define HIST_BLKS ((N_EDGES / 4 + 255) / 256) // 1563

// ---------------- device scratch (no allocations allowed) ----------------
// g_cnt is zero-initialized at load and re-zeroed at the END of each call
// (in k_head), so k_prehist can run pre+hist concurrently.
__device__ __half2 g_h0h[N_NODES * 16];     // h0 fp16 pairs (64B/row)
__device__ __half2 g_h1h[N_NODES * 32];     // h1 fp16 pairs (128B/row)
__device__ __half2 g_h2h[N_NODES * 32];     // h2 fp16 pairs (128B/row)
__device__ int     g_cnt[N_NODES];
__device__ int     g_rs[N_NODES];
__device__ int     g_rank[N_EDGES];         // per-edge rank within its dst (from hist)
__device__ int     g_adj[N_EDGES];
__device__ int     g_bsum[NB_SCAN + 8];
__device__ int     g_lo[N_GRAPHS + 1];

// ---------------- mma helpers ----------------
__device__ __forceinline__ uint32_t smem_u32(const void* p) {
    return (uint32_t)__cvta_generic_to_shared(p);
}
__device__ __forceinline__ void ldsm_x4(uint32_t& a0, uint32_t& a1,
                                        uint32_t& a2, uint32_t& a3, uint32_t addr) {
    asm volatile("ldmatrix.sync.aligned.m8n8.x4.shared.b16 {%0,%1,%2,%3}, [%4];"
                 : "=r"(a0), "=r"(a1), "=r"(a2), "=r"(a3) : "r"(addr));
}
__device__ __forceinline__ void ldsm_x2t(uint32_t& b0, uint32_t& b1, uint32_t addr) {
    asm volatile("ldmatrix.sync.aligned.m8n8.x2.trans.shared.b16 {%0,%1}, [%2];"
                 : "=r"(b0), "=r"(b1) : "r"(addr));
}
__device__ __forceinline__ void mma16816(float c[4], uint32_t a0, uint32_t a1,
                                         uint32_t a2, uint32_t a3,
                                         uint32_t b0, uint32_t b1) {
    asm volatile("mma.sync.aligned.m16n8k16.row.col.f32.f16.f16.f32 "
                 "{%0,%1,%2,%3}, {%4,%5,%6,%7}, {%8,%9}, {%0,%1,%2,%3};"
                 : "+f"(c[0]), "+f"(c[1]), "+f"(c[2]), "+f"(c[3])
                 : "r"(a0), "r"(a1), "r"(a2), "r"(a3), "r"(b0), "r"(b1));
}

// ---------------- fused pre (blocks 0..390) + hist+rank (rest) -----------
__global__ void k_prehist(const float* __restrict__ x,
                          const float* __restrict__ w,
                          const float* __restrict__ b,
                          const int* __restrict__ dst) {
    int t = threadIdx.x;
    if (blockIdx.x < PRE_BLKS) {
        __shared__ float sw[5 * 32];
        __shared__ float sb[32];
        if (t < 160) sw[t] = w[t];
        if (t < 32)  sb[t] = b[t];
        __syncthreads();
        int n = blockIdx.x * 256 + t;
        if (n >= N_NODES) return;
        float xi[5];
#pragma unroll
        for (int i = 0; i < 5; i++) xi[i] = x[n * 5 + i];
        __half2 hv[16];
#pragma unroll
        for (int j2 = 0; j2 < 16; j2++) {
            float o0 = sb[2 * j2], o1 = sb[2 * j2 + 1];
#pragma unroll
            for (int i = 0; i < 5; i++) {
                o0 += xi[i] * sw[i * 32 + 2 * j2];
                o1 += xi[i] * sw[i * 32 + 2 * j2 + 1];
            }
            hv[j2] = __floats2half2_rn(fmaxf(o0, 0.f), fmaxf(o1, 0.f));
        }
        uint4* dstp = (uint4*)&g_h0h[n * 16];
        dstp[0] = ((uint4*)hv)[0];
        dstp[1] = ((uint4*)hv)[1];
        dstp[2] = ((uint4*)hv)[2];
        dstp[3] = ((uint4*)hv)[3];
    } else {
        int i = (blockIdx.x - PRE_BLKS) * 256 + t;
        int e4 = i * 4;
        if (e4 + 3 < N_EDGES) {
            int4 d = *(const int4*)&dst[e4];
            int4 r;
            r.x = atomicAdd(&g_cnt[d.x], 1);
            r.y = atomicAdd(&g_cnt[d.y], 1);
            r.z = atomicAdd(&g_cnt[d.z], 1);
            r.w = atomicAdd(&g_cnt[d.w], 1);
            *(int4*)&g_rank[e4] = r;            // capture CSR slot for free
        } else if (e4 < N_EDGES) {
            for (int e = e4; e < N_EDGES; e++)
                g_rank[e] = atomicAdd(&g_cnt[dst[e]], 1);
        }
    }
}

__global__ void k_scan1() {
    __shared__ int wsum[8];
    int b = blockIdx.x, t = threadIdx.x;
    int lane = t & 31, w = t >> 5;
    int base = b * 1024 + t * 4;
    int v[4];
#pragma unroll
    for (int q = 0; q < 4; q++) v[q] = (base + q < N_NODES) ? g_cnt[base + q] : 0;
    int tot = v[0] + v[1] + v[2] + v[3];
    int sc = tot;
#pragma unroll
    for (int o = 1; o < 32; o <<= 1) {
        int x = __shfl_up_sync(0xffffffffu, sc, o);
        if (lane >= o) sc += x;
    }
    if (lane == 31) wsum[w] = sc;
    __syncthreads();
    if (t == 0) {
        int r = 0;
#pragma unroll
        for (int i = 0; i < 8; i++) { int x = wsum[i]; wsum[i] = r; r += x; }
        g_bsum[b] = r;
    }
    __syncthreads();
    int run = wsum[w] + (sc - tot);
#pragma unroll
    for (int q = 0; q < 4; q++) {
        if (base + q < N_NODES) g_rs[base + q] = run;
        run += v[q];
    }
}

// scan3 with embedded scan2 (each block redundantly scans the 98 sums) + bounds
__global__ void k_scan23(const int* __restrict__ batch) {
    __shared__ int psum[NB_SCAN];
    int t = threadIdx.x;
    if (t < NB_SCAN) psum[t] = g_bsum[t];
    __syncthreads();
    if (t == 0) {
        int r = 0;
#pragma unroll 7
        for (int i = 0; i < NB_SCAN; i++) { int x = psum[i]; psum[i] = r; r += x; }
    }
    __syncthreads();
    int i = blockIdx.x * 256 + t;
    if (i >= N_NODES) return;
    int v = g_rs[i] + psum[i >> 10];
    g_rs[i] = v;
    int b = batch[i];
    int bn = (i + 1 < N_NODES) ? batch[i + 1] : N_GRAPHS;
    if (i == 0)
        for (int g = 0; g <= b; g++) g_lo[g] = 0;
    for (int g = b + 1; g <= bn; g++) g_lo[g] = i + 1;
}

// atomic-free fill: position = rs[dst] + rank (rank captured during hist)
__global__ void k_fill(const int* __restrict__ src, const int* __restrict__ dst) {
    int i = blockIdx.x * blockDim.x + threadIdx.x;
    int e4 = i * 4;
    if (e4 + 3 < N_EDGES) {
        int4 s = *(const int4*)&src[e4];
        int4 d = *(const int4*)&dst[e4];
        int4 r = *(const int4*)&g_rank[e4];
        g_adj[g_rs[d.x] + r.x] = s.x;
        g_adj[g_rs[d.y] + r.y] = s.y;
        g_adj[g_rs[d.z] + r.z] = s.z;
        g_adj[g_rs[d.w] + r.w] = s.w;
    } else if (e4 < N_EDGES) {
        for (int e = e4; e < N_EDGES; e++)
            g_adj[g_rs[dst[e]] + g_rank[e]] = src[e];
    }
}

// ---------------- conv1: 16-deep gather + tensor-core combine ------------
__global__ void __launch_bounds__(256) k_conv1(const float* __restrict__ wl,
                                               const float* __restrict__ bl,
                                               const float* __restrict__ wr) {
    extern __shared__ char dyn[];
    half*  sB    = (half*)dyn;                                  // 64*72
    half*  sA    = (half*)(dyn + 64 * 72 * 2);                  // 8*16*72
    float* sbias = (float*)(dyn + 64 * 72 * 2 + 8 * 16 * 72 * 2);
    int t = threadIdx.x;
    for (int i = t; i < 64 * 64; i += 256) {
        int k = i >> 6, n = i & 63;
        float v = (k < 32) ? wl[k * 64 + n] : wr[(k - 32) * 64 + n];
        sB[k * 72 + n] = __float2half(v);
    }
    if (t < 64) sbias[t] = bl[t];
    __syncthreads();

    int lane = t & 31, warp = t >> 5;
    int tile = blockIdx.x * 8 + warp;
    if (tile >= N_TILES) return;
    int base = tile * 16;
    half2* sa2 = (half2*)(sA + warp * 16 * 72);   // row stride 36 half2
    int l15 = lane & 15;
    bool hihalf = lane >= 16;

    for (int r = 0; r < 16; r++) {
        int n = base + r;
        int rs = g_rs[n], d = g_cnt[n];
        float2 ac0 = make_float2(0.f, 0.f), ac1 = make_float2(0.f, 0.f);
        float2 ac2 = make_float2(0.f, 0.f), ac3 = make_float2(0.f, 0.f);
        for (int j = 0; j < d; j += 32) {
            int chunk = min(32, d - j);
            int idx = (lane < chunk) ? g_adj[rs + j + lane] : 0;
            int q = 0;
            for (; q + 15 < chunk; q += 16) {   // 8 loads/lane in flight
                int v[16];
#pragma unroll
                for (int u = 0; u < 16; u++) v[u] = __shfl_sync(0xffffffffu, idx, q + u);
                int s0 = hihalf ? v[1]  : v[0];
                int s1 = hihalf ? v[3]  : v[2];
                int s2 = hihalf ? v[5]  : v[4];
                int s3 = hihalf ? v[7]  : v[6];
                int s4 = hihalf ? v[9]  : v[8];
                int s5 = hihalf ? v[11] : v[10];
                int s6 = hihalf ? v[13] : v[12];
                int s7 = hihalf ? v[15] : v[14];
                float2 f0 = __half22float2(g_h0h[s0 * 16 + l15]);
                float2 f1 = __half22float2(g_h0h[s1 * 16 + l15]);
                float2 f2 = __half22float2(g_h0h[s2 * 16 + l15]);
                float2 f3 = __half22float2(g_h0h[s3 * 16 + l15]);
                float2 f4 = __half22float2(g_h0h[s4 * 16 + l15]);
                float2 f5 = __half22float2(g_h0h[s5 * 16 + l15]);
                float2 f6 = __half22float2(g_h0h[s6 * 16 + l15]);
                float2 f7 = __half22float2(g_h0h[s7 * 16 + l15]);
                ac0.x += f0.x + f4.x; ac0.y += f0.y + f4.y;
                ac1.x += f1.x + f5.x; ac1.y += f1.y + f5.y;
                ac2.x += f2.x + f6.x; ac2.y += f2.y + f6.y;
                ac3.x += f3.x + f7.x; ac3.y += f3.y + f7.y;
            }
            for (; q + 7 < chunk; q += 8) {
                int nA = __shfl_sync(0xffffffffu, idx, q);
                int nB = __shfl_sync(0xffffffffu, idx, q + 1);
                int nC = __shfl_sync(0xffffffffu, idx, q + 2);
                int nD = __shfl_sync(0xffffffffu, idx, q + 3);
                int nE = __shfl_sync(0xffffffffu, idx, q + 4);
                int nF = __shfl_sync(0xffffffffu, idx, q + 5);
                int nG = __shfl_sync(0xffffffffu, idx, q + 6);
                int nH = __shfl_sync(0xffffffffu, idx, q + 7);
                int s0 = hihalf ? nB : nA;
                int s1 = hihalf ? nD : nC;
                int s2 = hihalf ? nF : nE;
                int s3 = hihalf ? nH : nG;
                float2 f0 = __half22float2(g_h0h[s0 * 16 + l15]);
                float2 f1 = __half22float2(g_h0h[s1 * 16 + l15]);
                float2 f2 = __half22float2(g_h0h[s2 * 16 + l15]);
                float2 f3 = __half22float2(g_h0h[s3 * 16 + l15]);
                ac0.x += f0.x; ac0.y += f0.y;
                ac1.x += f1.x; ac1.y += f1.y;
                ac2.x += f2.x; ac2.y += f2.y;
                ac3.x += f3.x; ac3.y += f3.y;
            }
            for (; q + 1 < chunk; q += 2) {
                int nA = __shfl_sync(0xffffffffu, idx, q);
                int nB = __shfl_sync(0xffffffffu, idx, q + 1);
                int s0 = hihalf ? nB : nA;
                float2 f0 = __half22float2(g_h0h[s0 * 16 + l15]);
                ac0.x += f0.x; ac0.y += f0.y;
            }
            if (q < chunk) {
                int nA = __shfl_sync(0xffffffffu, idx, q);
                if (!hihalf) {
                    float2 f0 = __half22float2(g_h0h[nA * 16 + l15]);
                    ac0.x += f0.x; ac0.y += f0.y;
                }
            }
        }
        ac0.x += ac1.x + ac2.x + ac3.x;
        ac0.y += ac1.y + ac2.y + ac3.y;
        ac0.x += __shfl_xor_sync(0xffffffffu, ac0.x, 16);
        ac0.y += __shfl_xor_sync(0xffffffffu, ac0.y, 16);
        float inv = d > 0 ? 1.0f / (float)d : 0.0f;
        if (!hihalf) {
            sa2[r * 36 + l15]      = __floats2half2_rn(ac0.x * inv, ac0.y * inv);
            sa2[r * 36 + 16 + l15] = g_h0h[n * 16 + l15];
        }
    }
    __syncwarp();

    // GEMM: [16 x 64] @ [64 x 64], fp32 accum
    uint32_t aBase = smem_u32(sA + warp * 16 * 72) + (uint32_t)((lane & 15) * 144 + (lane >> 4) * 16);
    uint32_t bBase = smem_u32(sB) + (uint32_t)((lane & 15) * 144);
    float c[8][4];
#pragma unroll
    for (int nt = 0; nt < 8; nt++) { c[nt][0] = c[nt][1] = c[nt][2] = c[nt][3] = 0.f; }
#pragma unroll
    for (int kk = 0; kk < 4; kk++) {
        uint32_t a0, a1, a2, a3;
        ldsm_x4(a0, a1, a2, a3, aBase + kk * 32);
#pragma unroll
        for (int nt = 0; nt < 8; nt++) {
            uint32_t b0, b1;
            ldsm_x2t(b0, b1, bBase + (uint32_t)(kk * 16 * 144 + nt * 16));
            mma16816(c[nt], a0, a1, a2, a3, b0, b1);
        }
    }
    int q = lane & 3, rlo = lane >> 2;
    float ssl = 0.f, ssh = 0.f;
#pragma unroll
    for (int nt = 0; nt < 8; nt++) {
        float b0 = sbias[nt * 8 + q * 2], b1 = sbias[nt * 8 + q * 2 + 1];
        c[nt][0] += b0; c[nt][1] += b1; c[nt][2] += b0; c[nt][3] += b1;
        ssl += c[nt][0] * c[nt][0] + c[nt][1] * c[nt][1];
        ssh += c[nt][2] * c[nt][2] + c[nt][3] * c[nt][3];
    }
    ssl += __shfl_xor_sync(0xffffffffu, ssl, 1);
    ssl += __shfl_xor_sync(0xffffffffu, ssl, 2);
    ssh += __shfl_xor_sync(0xffffffffu, ssh, 1);
    ssh += __shfl_xor_sync(0xffffffffu, ssh, 2);
    float il = 1.0f / fmaxf(sqrtf(ssl), 1e-12f);
    float ih = 1.0f / fmaxf(sqrtf(ssh), 1e-12f);
    int nlo = base + rlo, nhi = nlo + 8;
#pragma unroll
    for (int nt = 0; nt < 8; nt++) {
        g_h1h[nlo * 32 + nt * 4 + q] =
            __floats2half2_rn(fmaxf(c[nt][0] * il, 0.f), fmaxf(c[nt][1] * il, 0.f));
        g_h1h[nhi * 32 + nt * 4 + q] =
            __floats2half2_rn(fmaxf(c[nt][2] * ih, 0.f), fmaxf(c[nt][3] * ih, 0.f));
    }
}

// ---------------- conv2: 16-deep gather + tensor-core combine ------------
__global__ void __launch_bounds__(256) k_conv2(const float* __restrict__ wl,
                                               const float* __restrict__ bl,
                                               const float* __restrict__ wr) {
    extern __shared__ char dyn[];
    half*  sB    = (half*)dyn;                                   // 128*72
    half*  sA    = (half*)(dyn + 128 * 72 * 2);                  // 8*16*136
    float* sbias = (float*)(dyn + 128 * 72 * 2 + 8 * 16 * 136 * 2);
    int t = threadIdx.x;
    for (int i = t; i < 128 * 64; i += 256) {
        int k = i >> 6, n = i & 63;
        float v = (k < 64) ? wl[k * 64 + n] : wr[(k - 64) * 64 + n];
        sB[k * 72 + n] = __float2half(v);
    }
    if (t < 64) sbias[t] = bl[t];
    __syncthreads();

    int lane = t & 31, warp = t >> 5;
    int tile = blockIdx.x * 8 + warp;
    if (tile >= N_TILES) return;
    int base = tile * 16;
    half2* sa2 = (half2*)(sA + warp * 16 * 136);   // row stride 68 half2

    for (int r = 0; r < 16; r++) {
        int n = base + r;
        int rs = g_rs[n], d = g_cnt[n];
        float a0 = 0.f, b0 = 0.f, a1 = 0.f, b1 = 0.f;
        float a2 = 0.f, b2 = 0.f, a3 = 0.f, b3 = 0.f;
        for (int j = 0; j < d; j += 32) {
            int chunk = min(32, d - j);
            int idx = (lane < chunk) ? g_adj[rs + j + lane] : 0;
            int q = 0;
            for (; q + 15 < chunk; q += 16) {   // 16 loads/lane in flight
                int m[16];
#pragma unroll
                for (int u = 0; u < 16; u++) m[u] = __shfl_sync(0xffffffffu, idx, q + u);
                float2 f[16];
#pragma unroll
                for (int u = 0; u < 16; u++) f[u] = __half22float2(g_h1h[m[u] * 32 + lane]);
#pragma unroll
                for (int u = 0; u < 16; u += 4) {
                    a0 += f[u].x;     b0 += f[u].y;
                    a1 += f[u + 1].x; b1 += f[u + 1].y;
                    a2 += f[u + 2].x; b2 += f[u + 2].y;
                    a3 += f[u + 3].x; b3 += f[u + 3].y;
                }
            }
            for (; q + 3 < chunk; q += 4) {
                int m0 = __shfl_sync(0xffffffffu, idx, q);
                int m1 = __shfl_sync(0xffffffffu, idx, q + 1);
                int m2 = __shfl_sync(0xffffffffu, idx, q + 2);
                int m3 = __shfl_sync(0xffffffffu, idx, q + 3);
                float2 f0 = __half22float2(g_h1h[m0 * 32 + lane]);
                float2 f1 = __half22float2(g_h1h[m1 * 32 + lane]);
                float2 f2 = __half22float2(g_h1h[m2 * 32 + lane]);
                float2 f3 = __half22float2(g_h1h[m3 * 32 + lane]);
                a0 += f0.x; b0 += f0.y;
                a1 += f1.x; b1 += f1.y;
                a2 += f2.x; b2 += f2.y;
                a3 += f3.x; b3 += f3.y;
            }
            for (; q < chunk; q++) {
                int m0 = __shfl_sync(0xffffffffu, idx, q);
                float2 f0 = __half22float2(g_h1h[m0 * 32 + lane]);
                a0 += f0.x; b0 += f0.y;
            }
        }
        float inv = d > 0 ? 1.0f / (float)d : 0.0f;
        sa2[r * 68 + lane] =
            __floats2half2_rn((a0 + a1 + a2 + a3) * inv, (b0 + b1 + b2 + b3) * inv);
        sa2[r * 68 + 32 + lane] = g_h1h[n * 32 + lane];
    }
    __syncwarp();

    // GEMM: [16 x 128] @ [128 x 64], fp32 accum
    uint32_t aBase = smem_u32(sA + warp * 16 * 136) + (uint32_t)((lane & 15) * 272 + (lane >> 4) * 16);
    uint32_t bBase = smem_u32(sB) + (uint32_t)((lane & 15) * 144);
    float c[8][4];
#pragma unroll
    for (int nt = 0; nt < 8; nt++) { c[nt][0] = c[nt][1] = c[nt][2] = c[nt][3] = 0.f; }
#pragma unroll
    for (int kk = 0; kk < 8; kk++) {
        uint32_t a0, a1, a2, a3;
        ldsm_x4(a0, a1, a2, a3, aBase + kk * 32);
#pragma unroll
        for (int nt = 0; nt < 8; nt++) {
            uint32_t b0, b1;
            ldsm_x2t(b0, b1, bBase + (uint32_t)(kk * 16 * 144 + nt * 16));
            mma16816(c[nt], a0, a1, a2, a3, b0, b1);
        }
    }
    int q = lane & 3, rlo = lane >> 2;
    float ssl = 0.f, ssh = 0.f;
#pragma unroll
    for (int nt = 0; nt < 8; nt++) {
        float bb0 = sbias[nt * 8 + q * 2], bb1 = sbias[nt * 8 + q * 2 + 1];
        c[nt][0] += bb0; c[nt][1] += bb1; c[nt][2] += bb0; c[nt][3] += bb1;
        ssl += c[nt][0] * c[nt][0] + c[nt][1] * c[nt][1];
        ssh += c[nt][2] * c[nt][2] + c[nt][3] * c[nt][3];
    }
    ssl += __shfl_xor_sync(0xffffffffu, ssl, 1);
    ssl += __shfl_xor_sync(0xffffffffu, ssl, 2);
    ssh += __shfl_xor_sync(0xffffffffu, ssh, 1);
    ssh += __shfl_xor_sync(0xffffffffu, ssh, 2);
    float il = 1.0f / fmaxf(sqrtf(ssl), 1e-12f);
    float ih = 1.0f / fmaxf(sqrtf(ssh), 1e-12f);
    int nlo = base + rlo, nhi = nlo + 8;
#pragma unroll
    for (int nt = 0; nt < 8; nt++) {
        g_h2h[nlo * 32 + nt * 4 + q] =
            __floats2half2_rn(fmaxf(c[nt][0] * il, 0.f), fmaxf(c[nt][1] * il, 0.f));
        g_h2h[nhi * 32 + nt * 4 + q] =
            __floats2half2_rn(fmaxf(c[nt][2] * ih, 0.f), fmaxf(c[nt][3] * ih, 0.f));
    }
}

// ---------------- head: pool + MLP; ALSO re-zeroes g_cnt for next call ---
__global__ void k_head(const float* __restrict__ p1w, const float* __restrict__ p1b,
                       const float* __restrict__ p2w, const float* __restrict__ p2b,
                       const float* __restrict__ ow,  const float* __restrict__ ob,
                       float* __restrict__ out) {
    __shared__ float part[4 * 64];
    __shared__ float sg[64], t1[64], t2[16];
    int g = blockIdx.x, t = threadIdx.x;
    int zi = g * 256 + t;
    if (zi < N_NODES) g_cnt[zi] = 0;

    int lo = g_lo[g], hi = g_lo[g + 1];
    int f = t & 63, r = t >> 6;
    float s = 0.f;
    for (int n = lo + r; n < hi; n += 4) {
        __half2 v = g_h2h[n * 32 + (f >> 1)];
        s += (f & 1) ? __half2float(__high2half(v)) : __half2float(__low2half(v));
    }
    part[r * 64 + f] = s;
    __syncthreads();
    if (t < 64) {
        float tot = part[t] + part[64 + t] + part[128 + t] + part[192 + t];
        float cnt = (float)(hi - lo);
        sg[t] = tot / fmaxf(cnt, 1.0f);
    }
    __syncthreads();
    if (t < 64) {
        float s1 = p1b[t];
#pragma unroll 8
        for (int k = 0; k < 64; k++) s1 += sg[k] * p1w[k * 64 + t];
        t1[t] = fmaxf(s1, 0.f);
    }
    __syncthreads();
    if (t < 16) {
        float s2 = p2b[t];
#pragma unroll 8
        for (int k = 0; k < 64; k++) s2 += t1[k] * p2w[k * 16 + t];
        t2[t] = fmaxf(s2, 0.f);
    }
    __syncthreads();
    if (t == 0) {
        float o = ob[0];
#pragma unroll
        for (int k = 0; k < 16; k++) o += t2[k] * ow[k];
        out[g] = o;
    }
}

// ---------------- launch ----------------
extern "C" void kernel_launch(void* const* d_in, const int* in_sizes, int n_in,
                              void* d_out, int out_size) {
    const float* x     = (const float*)d_in[0];
    const int*   ei    = (const int*)d_in[1];
    const int*   batch = (const int*)d_in[2];
    int base = (n_in >= 18 && in_sizes[3] == 1) ? 4 : 3;
    const float* pre_w = (const float*)d_in[base + 0];
    const float* pre_b = (const float*)d_in[base + 1];
    const float* c1_wl = (const float*)d_in[base + 2];
    const float* c1_bl = (const float*)d_in[base + 3];
    const float* c1_wr = (const float*)d_in[base + 4];
    const float* c2_wl = (const float*)d_in[base + 5];
    const float* c2_bl = (const float*)d_in[base + 6];
    const float* c2_wr = (const float*)d_in[base + 7];
    const float* p1_w  = (const float*)d_in[base + 8];
    const float* p1_b  = (const float*)d_in[base + 9];
    const float* p2_w  = (const float*)d_in[base + 10];
    const float* p2_b  = (const float*)d_in[base + 11];
    const float* o_w   = (const float*)d_in[base + 12];
    const float* o_b   = (const float*)d_in[base + 13];

    const int* src = ei;
    const int* dst = ei + N_EDGES;
    float* out = (float*)d_out;

    const size_t smem1 = 64 * 72 * 2 + 8 * 16 * 72 * 2 + 256;     // 27904
    const size_t smem2 = 128 * 72 * 2 + 8 * 16 * 136 * 2 + 256;   // 53504
    cudaFuncSetAttribute(k_conv1, cudaFuncAttributeMaxDynamicSharedMemorySize, (int)smem1);
    cudaFuncSetAttribute(k_conv2, cudaFuncAttributeMaxDynamicSharedMemorySize, (int)smem2);

    const int T = 256;
    k_prehist<<<PRE_BLKS + HIST_BLKS, T>>>(x, pre_w, pre_b, dst);
    k_scan1<<<NB_SCAN, 256>>>();
    k_scan23<<<PRE_BLKS, 256>>>(batch);
    k_fill<<<HIST_BLKS, T>>>(src, dst);     // 4 edges/thread, atomic-free

    int nblk = (N_TILES + 7) / 8;   // 782
    k_conv1<<<nblk, 256, smem1>>>(c1_wl, c1_bl, c1_wr);
    k_conv2<<<nblk, 256, smem2>>>(c2_wl, c2_bl, c2_wr);

    k_head<<<N_GRAPHS, 256>>>(p1_w, p1_b, p2_w, p2_b, o_w, o_b, out);
    (void)out_size;
}